// round 1
// baseline (speedup 1.0000x reference)
#include <cuda_runtime.h>

// ---------------------------------------------------------------------------
// InferCellV1 on GB300 — fp32 CUDA-core implementation with the prefix trick:
// the 8-way input-channel-width mixture in nor_conv's second conv is computed
// as prefix sums over 8-channel groups of ONE conv (8x FLOP reduction).
// ---------------------------------------------------------------------------

#define BATCH 64
#define CH    64
#define HWPIX 1024   // 32*32
#define EPSV  1e-5f

// Scratch (device globals are the sanctioned scratch mechanism)
__device__ float  g_C1[(size_t)BATCH * CH * HWPIX];          // 16.7 MB conv1 out
__device__ float  g_P [(size_t)8 * BATCH * CH * HWPIX];      // 134 MB prefix outs
__device__ float  g_N1[(size_t)BATCH * CH * HWPIX];
__device__ float  g_N2[(size_t)BATCH * CH * HWPIX];
__device__ float2 g_part1[64 * 8];                           // stage-1 stat partials
__device__ float2 g_part2[8 * 64 * 4];                       // stage-2 stat partials
__device__ float  g_scale1[64], g_shift1[64];
__device__ float  g_scaleP[8 * 64];
__device__ float  g_biasP[64];
__device__ float  g_m1v[64], g_cmv[64];

// m1[c] = suffix sum of a1 from floor(c/8); cm[c] = m1(a1)[c]*m1(a2)[c]
__global__ void prep_kernel(const float* __restrict__ a1,
                            const float* __restrict__ a2) {
    int c = threadIdx.x;
    int g = c >> 3;
    float s1 = 0.f, s2 = 0.f;
    for (int i = g; i < 8; ++i) { s1 += a1[i]; s2 += a2[i]; }
    g_m1v[c] = s1;
    g_cmv[c] = s1 * s2;
}

// ---------------------------------------------------------------------------
// Direct 3x3 conv, B=64, 64->64 ch, 32x32, SAME padding.
// Block: one image b, 16 output channels, full 32x32. 256 threads.
// Thread: 4 pixels (rows ty, ty+8, ty+16, ty+24; col tx) x 16 out channels.
// STAGE 1: input = relu(src), writes g_C1.
// STAGE 2: input = affine(g_C1) (fused BN+mask), writes prefix P_g at every
//          8-input-channel group boundary (the width-mixture candidates).
// SRC: 0 = kernel param, 1 = g_N1, 2 = g_N2  (stage 1 only)
// ---------------------------------------------------------------------------
template <int STAGE, int SRC>
__global__ __launch_bounds__(256, 2)
void conv_kernel(const float* __restrict__ in, const float* __restrict__ w) {
    __shared__ float sIn[8 * 34 * 34];   // 8 input ch with halo
    __shared__ float sW[16 * 8 * 9];     // 16 oc x 8 ci x 9 taps

    const int b   = blockIdx.x >> 2;
    const int oc0 = (blockIdx.x & 3) << 4;
    const int t   = threadIdx.x;
    const int tx  = t & 31;
    const int ty  = t >> 5;

    float acc[4][16];
#pragma unroll
    for (int p = 0; p < 4; ++p)
#pragma unroll
        for (int o = 0; o < 16; ++o) acc[p][o] = 0.f;

    const float* src = (STAGE == 2) ? g_C1
                     : (SRC == 0)   ? in
                     : (SRC == 1)   ? g_N1
                                    : g_N2;

    for (int cc = 0; cc < 8; ++cc) {
        const int cbase = cc * 8;
        // stage input tile (with zero halo)
        for (int idx = t; idx < 8 * 34 * 34; idx += 256) {
            int ci = idx / 1156;
            int r  = idx - ci * 1156;
            int y  = r / 34;
            int x  = r - y * 34;
            int gy = y - 1, gx = x - 1;
            float v = 0.f;
            if ((unsigned)gy < 32u && (unsigned)gx < 32u) {
                float raw = src[(((size_t)b * 64 + cbase + ci) << 10) + (gy << 5) + gx];
                if (STAGE == 1) v = fmaxf(raw, 0.f);
                else            v = fmaf(raw, g_scale1[cbase + ci], g_shift1[cbase + ci]);
            }
            sIn[idx] = v;
        }
        // weights for this 16-oc x 8-ci chunk
        for (int idx = t; idx < 16 * 72; idx += 256) {
            int oc = idx / 72;
            int r  = idx - oc * 72;  // r = ci*9 + tap
            sW[idx] = w[((size_t)(oc0 + oc) * 64 + cbase) * 9 + r];
        }
        __syncthreads();

#pragma unroll
        for (int ci = 0; ci < 8; ++ci) {
#pragma unroll
            for (int ky = 0; ky < 3; ++ky) {
#pragma unroll
                for (int kx = 0; kx < 3; ++kx) {
                    float wv[16];
#pragma unroll
                    for (int o = 0; o < 16; ++o)
                        wv[o] = sW[o * 72 + ci * 9 + ky * 3 + kx];
#pragma unroll
                    for (int p = 0; p < 4; ++p) {
                        float iv = sIn[ci * 1156 + (ty + 8 * p + ky) * 34 + tx + kx];
#pragma unroll
                        for (int o = 0; o < 16; ++o)
                            acc[p][o] = fmaf(iv, wv[o], acc[p][o]);
                    }
                }
            }
        }

        if (STAGE == 2) {
            // group boundary: acc is the prefix P_cc for the width candidate cc
#pragma unroll
            for (int p = 0; p < 4; ++p) {
                int pix = ((ty + 8 * p) << 5) + tx;
#pragma unroll
                for (int o = 0; o < 16; ++o)
                    g_P[(((size_t)cc * 64 + b) * 64 + oc0 + o) * 1024 + pix] = acc[p][o];
            }
        }
        __syncthreads();
    }

    if (STAGE == 1) {
#pragma unroll
        for (int p = 0; p < 4; ++p) {
            int pix = ((ty + 8 * p) << 5) + tx;
#pragma unroll
            for (int o = 0; o < 16; ++o)
                g_C1[(((size_t)b * 64 + oc0 + o) << 10) + pix] = acc[p][o];
        }
    }
}

// ---------------------------------------------------------------------------
// Statistics (per-channel sums / sumsq), atomic-free two-stage reductions
// ---------------------------------------------------------------------------
__global__ void stats1_kernel() {  // grid 512: c = bx&63, bchunk = bx>>6
    __shared__ float rs[256], rq[256];
    int bx = blockIdx.x, c = bx & 63, chunk = bx >> 6;
    int t = threadIdx.x;
    float s = 0.f, q = 0.f;
    for (int b = chunk * 8; b < chunk * 8 + 8; ++b) {
        const float* p = g_C1 + (((size_t)b * 64 + c) << 10);
        for (int i = t; i < 1024; i += 256) { float v = p[i]; s += v; q += v * v; }
    }
    rs[t] = s; rq[t] = q; __syncthreads();
    for (int off = 128; off; off >>= 1) {
        if (t < off) { rs[t] += rs[t + off]; rq[t] += rq[t + off]; }
        __syncthreads();
    }
    if (t == 0) g_part1[c * 8 + chunk] = make_float2(rs[0], rq[0]);
}

__global__ void fin1_kernel() {  // <<<1,64>>>
    int c = threadIdx.x;
    float s = 0.f, q = 0.f;
    for (int j = 0; j < 8; ++j) { float2 v = g_part1[c * 8 + j]; s += v.x; q += v.y; }
    const float invN = 1.f / 65536.f;
    float mu   = s * invN;
    float var  = q * invN - mu * mu;
    float rstd = rsqrtf(var + EPSV);
    float sc   = rstd * g_m1v[c];    // BN rstd * soft channel mask m1
    g_scale1[c] = sc;
    g_shift1[c] = -mu * sc;
}

__global__ void stats2_kernel() {  // grid 2048: k=bx>>8, c=(bx>>2)&63, chunk=bx&3
    __shared__ float rs[256], rq[256];
    int bx = blockIdx.x;
    int k = bx >> 8, c = (bx >> 2) & 63, chunk = bx & 3;
    int t = threadIdx.x;
    float s = 0.f, q = 0.f;
    for (int b = chunk * 16; b < chunk * 16 + 16; ++b) {
        const float* p = g_P + (((size_t)k * 64 + b) * 64 + c) * 1024;
        for (int i = t; i < 1024; i += 256) { float v = p[i]; s += v; q += v * v; }
    }
    rs[t] = s; rq[t] = q; __syncthreads();
    for (int off = 128; off; off >>= 1) {
        if (t < off) { rs[t] += rs[t + off]; rq[t] += rq[t + off]; }
        __syncthreads();
    }
    if (t == 0) g_part2[(k * 64 + c) * 4 + chunk] = make_float2(rs[0], rq[0]);
}

__global__ void fin2_kernel(const float* __restrict__ a2) {  // <<<1,64>>>
    int c = threadIdx.x;
    const float invN = 1.f / 65536.f;
    float bias = 0.f;
    for (int k = 0; k < 8; ++k) {
        float s = 0.f, q = 0.f;
        for (int j = 0; j < 4; ++j) { float2 v = g_part2[(k * 64 + c) * 4 + j]; s += v.x; q += v.y; }
        float mu  = s * invN;
        float var = q * invN - mu * mu;
        float wk  = a2[k] * rsqrtf(var + EPSV);
        g_scaleP[k * 64 + c] = wk;
        bias -= wk * mu;
    }
    g_biasP[c] = bias;
}

// ---------------------------------------------------------------------------
// Combine: out = sum_k scaleP[k,c] * P_k + biasP[c], fused with graph edges:
// MODE 0: -> g_N1
// MODE 1: -> g_N2, + avgpool3(g_N1)*cm (count_include_pad=False)
// MODE 2: -> out,  + xin*cm  (skip edge)
// MODE 3: -> out += (accumulate)
// ---------------------------------------------------------------------------
template <int MODE>
__global__ void combine_kernel(const float* __restrict__ xin, float* __restrict__ out) {
    int bc = blockIdx.x;
    int b = bc >> 6, c = bc & 63;
    int t = threadIdx.x;
    float sp[8];
#pragma unroll
    for (int k = 0; k < 8; ++k) sp[k] = g_scaleP[k * 64 + c];
    float bias = g_biasP[c];
    float cmv  = g_cmv[c];
    size_t base = ((size_t)b * 64 + c) << 10;

    for (int p = t; p < 1024; p += 256) {
        float acc = bias;
#pragma unroll
        for (int k = 0; k < 8; ++k)
            acc = fmaf(sp[k], g_P[(((size_t)k * 64 + b) * 64 + c) * 1024 + p], acc);

        if (MODE == 0) g_N1[base + p] = acc;
        if (MODE == 1) {
            int y = p >> 5, x = p & 31;
            int y0 = max(y - 1, 0), y1 = min(y + 1, 31);
            int x0 = max(x - 1, 0), x1 = min(x + 1, 31);
            float s = 0.f;
            for (int yy = y0; yy <= y1; ++yy)
                for (int xx = x0; xx <= x1; ++xx)
                    s += g_N1[base + (yy << 5) + xx];
            float cnt = (float)((y1 - y0 + 1) * (x1 - x0 + 1));
            g_N2[base + p] = acc + (s / cnt) * cmv;
        }
        if (MODE == 2) out[base + p] = acc + xin[base + p] * cmv;
        if (MODE == 3) out[base + p] += acc;
    }
}

// ---------------------------------------------------------------------------
extern "C" void kernel_launch(void* const* d_in, const int* in_sizes, int n_in,
                              void* d_out, int out_size) {
    (void)in_sizes; (void)n_in; (void)out_size;
    const float* x    = (const float*)d_in[0];
    const float* a1   = (const float*)d_in[1];
    const float* a2   = (const float*)d_in[2];
    const float* W1_0 = (const float*)d_in[3];
    const float* W2_0 = (const float*)d_in[4];
    const float* W1_1 = (const float*)d_in[5];
    const float* W2_1 = (const float*)d_in[6];
    const float* W1_4 = (const float*)d_in[7];
    const float* W2_4 = (const float*)d_in[8];
    const float* W1_5 = (const float*)d_in[9];
    const float* W1_5b= (const float*)d_in[10];  // W2_5
    float* out = (float*)d_out;

    prep_kernel<<<1, 64>>>(a1, a2);

    // n1 = nor_conv(x, W1_0, W2_0)
    conv_kernel<1, 0><<<256, 256>>>(x, W1_0);
    stats1_kernel<<<512, 256>>>();
    fin1_kernel<<<1, 64>>>();
    conv_kernel<2, 0><<<256, 256>>>(x, W2_0);
    stats2_kernel<<<2048, 256>>>();
    fin2_kernel<<<1, 64>>>(a2);
    combine_kernel<0><<<4096, 256>>>(nullptr, nullptr);

    // n2 = nor_conv(x, W1_1, W2_1) + avgpool3(n1)*cm
    conv_kernel<1, 0><<<256, 256>>>(x, W1_1);
    stats1_kernel<<<512, 256>>>();
    fin1_kernel<<<1, 64>>>();
    conv_kernel<2, 0><<<256, 256>>>(x, W2_1);
    stats2_kernel<<<2048, 256>>>();
    fin2_kernel<<<1, 64>>>(a2);
    combine_kernel<1><<<4096, 256>>>(nullptr, nullptr);

    // out = x*cm + nor_conv(n1, W1_4, W2_4)
    conv_kernel<1, 1><<<256, 256>>>(nullptr, W1_4);
    stats1_kernel<<<512, 256>>>();
    fin1_kernel<<<1, 64>>>();
    conv_kernel<2, 0><<<256, 256>>>(nullptr, W2_4);
    stats2_kernel<<<2048, 256>>>();
    fin2_kernel<<<1, 64>>>(a2);
    combine_kernel<2><<<4096, 256>>>(x, out);

    // out += nor_conv(n2, W1_5, W2_5)
    conv_kernel<1, 2><<<256, 256>>>(nullptr, W1_5);
    stats1_kernel<<<512, 256>>>();
    fin1_kernel<<<1, 64>>>();
    conv_kernel<2, 0><<<256, 256>>>(nullptr, W1_5b);
    stats2_kernel<<<2048, 256>>>();
    fin2_kernel<<<1, 64>>>(a2);
    combine_kernel<3><<<4096, 256>>>(nullptr, out);
}

// round 2
// speedup vs baseline: 1.1652x; 1.1652x over previous
#include <cuda_runtime.h>

// ---------------------------------------------------------------------------
// InferCellV1 on GB300 — fp32 with (a) prefix trick (8x FLOP cut), (b) packed
// fma.rn.f32x2 (2x FMA pipe), (c) BN stats fused into conv kernels,
// (d) float4 combine.
// ---------------------------------------------------------------------------

typedef unsigned long long u64;
#define EPSV 1e-5f

__device__ float  g_C1[(size_t)64 * 64 * 1024];          // conv1 out (16.7 MB)
__device__ float  g_P [(size_t)8 * 64 * 64 * 1024];      // prefix outs (134 MB)
__device__ float  g_N1[(size_t)64 * 64 * 1024];
__device__ float  g_N2[(size_t)64 * 64 * 1024];
__device__ float2 g_part1[64 * 64];                      // [c][b]
__device__ float2 g_part2[8 * 64 * 64];                  // [k][c][b]
__device__ float  g_scale1[64], g_shift1[64];
__device__ float  g_scaleP[8 * 64];
__device__ float  g_biasP[64];
__device__ float  g_m1v[64], g_cmv[64];

__device__ __forceinline__ u64 fma2(u64 a, u64 b, u64 c) {
    u64 d; asm("fma.rn.f32x2 %0, %1, %2, %3;" : "=l"(d) : "l"(a), "l"(b), "l"(c)); return d;
}
__device__ __forceinline__ u64 pack2(float x, float y) {
    u64 d; asm("mov.b64 %0, {%1, %2};" : "=l"(d) : "f"(x), "f"(y)); return d;
}
__device__ __forceinline__ float2 unpack2(u64 v) {
    float2 r; asm("mov.b64 {%0, %1}, %2;" : "=f"(r.x), "=f"(r.y) : "l"(v)); return r;
}

__global__ void prep_kernel(const float* __restrict__ a1, const float* __restrict__ a2) {
    int c = threadIdx.x;
    int g = c >> 3;
    float s1 = 0.f, s2 = 0.f;
    for (int i = g; i < 8; ++i) { s1 += a1[i]; s2 += a2[i]; }
    g_m1v[c] = s1;
    g_cmv[c] = s1 * s2;
}

// ---------------------------------------------------------------------------
// Direct 3x3 conv, one image b x 16 output channels x 32x32 per block.
// Thread: 4 pixels (rows ty+8p, col tx) x 16 oc, accumulated as 8 f32x2 pairs.
// STAGE 1: relu(src) -> conv -> g_C1, fused per-(c,b) stat partials.
// STAGE 2: affine(g_C1) -> conv, prefix P_k emitted per 8-ci group, fused
//          per-(k,c,b) stat partials.
// ---------------------------------------------------------------------------
template <int STAGE, int SRC>
__global__ __launch_bounds__(256, 2)
void conv_kernel(const float* __restrict__ in, const float* __restrict__ w) {
    __shared__ float sIn[9248];        // 8ci x 34x34 halo tile; reused as stat scratch
    __shared__ float sW[1152];         // [ci*9+tap][16 oc]  (oc pairs -> LDS.64)
    __shared__ float sSc[64], sSh[64];

    const int b   = blockIdx.x >> 2;
    const int oc0 = (blockIdx.x & 3) << 4;
    const int t   = threadIdx.x;
    const int tx  = t & 31;
    const int ty  = t >> 5;

    if (STAGE == 2 && t < 64) { sSc[t] = g_scale1[t]; sSh[t] = g_shift1[t]; }

    u64 acc2[4][8];
#pragma unroll
    for (int p = 0; p < 4; ++p)
#pragma unroll
        for (int o2 = 0; o2 < 8; ++o2) acc2[p][o2] = 0ull;

    const float* src = (STAGE == 2) ? g_C1
                     : (SRC == 0)   ? in
                     : (SRC == 1)   ? g_N1
                                    : g_N2;

    for (int cc = 0; cc < 8; ++cc) {
        const int cbase = cc << 3;
        __syncthreads();   // sIn is free to overwrite (covers prior group's readers)

        for (int idx = t; idx < 9248; idx += 256) {
            int ci = idx / 1156;
            int r  = idx - ci * 1156;
            int y  = r / 34;
            int x  = r - y * 34;
            int gy = y - 1, gx = x - 1;
            float v = 0.f;
            if ((unsigned)gy < 32u && (unsigned)gx < 32u) {
                float raw = src[(((size_t)b * 64 + cbase + ci) << 10) + (gy << 5) + gx];
                v = (STAGE == 1) ? fmaxf(raw, 0.f)
                                 : fmaf(raw, sSc[cbase + ci], sSh[cbase + ci]);
            }
            sIn[idx] = v;
        }
        for (int idx = t; idx < 1152; idx += 256) {
            int oc = idx & 15;
            int r  = idx >> 4;          // ci*9 + tap
            int ci = r / 9;
            int tap = r - ci * 9;
            sW[idx] = w[((size_t)(oc0 + oc) * 64 + cbase + ci) * 9 + tap];
        }
        __syncthreads();

#pragma unroll
        for (int ci = 0; ci < 8; ++ci) {
#pragma unroll
            for (int ky = 0; ky < 3; ++ky) {
#pragma unroll
                for (int kx = 0; kx < 3; ++kx) {
                    const float* wrow = &sW[(ci * 9 + ky * 3 + kx) << 4];
                    u64 wp[8];
#pragma unroll
                    for (int o2 = 0; o2 < 8; ++o2)
                        wp[o2] = *reinterpret_cast<const u64*>(wrow + (o2 << 1));
#pragma unroll
                    for (int p = 0; p < 4; ++p) {
                        float iv = sIn[ci * 1156 + (ty + (p << 3) + ky) * 34 + tx + kx];
                        u64 iv2 = pack2(iv, iv);
#pragma unroll
                        for (int o2 = 0; o2 < 8; ++o2)
                            acc2[p][o2] = fma2(iv2, wp[o2], acc2[p][o2]);
                    }
                }
            }
        }

        if (STAGE == 2) {
            // acc2 now holds prefix P_cc. Emit it + fused stat partials.
            float s[16], q[16];
#pragma unroll
            for (int o = 0; o < 16; ++o) { s[o] = 0.f; q[o] = 0.f; }
#pragma unroll
            for (int p = 0; p < 4; ++p) {
                int pix = ((ty + (p << 3)) << 5) + tx;
#pragma unroll
                for (int o2 = 0; o2 < 8; ++o2) {
                    float2 v = unpack2(acc2[p][o2]);
                    size_t base = (((size_t)cc * 64 + b) * 64 + oc0 + (o2 << 1)) * 1024 + pix;
                    g_P[base]        = v.x;
                    g_P[base + 1024] = v.y;
                    s[2 * o2]     += v.x; q[2 * o2]     += v.x * v.x;
                    s[2 * o2 + 1] += v.y; q[2 * o2 + 1] += v.y * v.y;
                }
            }
            __syncthreads();           // done reading sIn for conv
#pragma unroll
            for (int o = 0; o < 16; ++o) { sIn[o * 256 + t] = s[o]; sIn[4096 + o * 256 + t] = q[o]; }
            __syncthreads();
            for (int off = 128; off; off >>= 1) {
                if (t < off) {
#pragma unroll
                    for (int o = 0; o < 16; ++o) {
                        sIn[o * 256 + t]        += sIn[o * 256 + t + off];
                        sIn[4096 + o * 256 + t] += sIn[4096 + o * 256 + t + off];
                    }
                }
                __syncthreads();
            }
            if (t < 16)
                g_part2[(cc * 64 + oc0 + t) * 64 + b] =
                    make_float2(sIn[t * 256], sIn[4096 + t * 256]);
        }
    }

    if (STAGE == 1) {
        float s[16], q[16];
#pragma unroll
        for (int o = 0; o < 16; ++o) { s[o] = 0.f; q[o] = 0.f; }
#pragma unroll
        for (int p = 0; p < 4; ++p) {
            int pix = ((ty + (p << 3)) << 5) + tx;
#pragma unroll
            for (int o2 = 0; o2 < 8; ++o2) {
                float2 v = unpack2(acc2[p][o2]);
                size_t base = (((size_t)b * 64 + oc0 + (o2 << 1)) << 10) + pix;
                g_C1[base]        = v.x;
                g_C1[base + 1024] = v.y;
                s[2 * o2]     += v.x; q[2 * o2]     += v.x * v.x;
                s[2 * o2 + 1] += v.y; q[2 * o2 + 1] += v.y * v.y;
            }
        }
        __syncthreads();
#pragma unroll
        for (int o = 0; o < 16; ++o) { sIn[o * 256 + t] = s[o]; sIn[4096 + o * 256 + t] = q[o]; }
        __syncthreads();
        for (int off = 128; off; off >>= 1) {
            if (t < off) {
#pragma unroll
                for (int o = 0; o < 16; ++o) {
                    sIn[o * 256 + t]        += sIn[o * 256 + t + off];
                    sIn[4096 + o * 256 + t] += sIn[4096 + o * 256 + t + off];
                }
            }
            __syncthreads();
        }
        if (t < 16)
            g_part1[(oc0 + t) * 64 + b] = make_float2(sIn[t * 256], sIn[4096 + t * 256]);
    }
}

// ---------------------------------------------------------------------------
__global__ void fin1_kernel() {  // <<<1,64>>>
    int c = threadIdx.x;
    float s = 0.f, q = 0.f;
    for (int b = 0; b < 64; ++b) { float2 v = g_part1[c * 64 + b]; s += v.x; q += v.y; }
    const float invN = 1.f / 65536.f;
    float mu   = s * invN;
    float var  = q * invN - mu * mu;
    float sc   = rsqrtf(var + EPSV) * g_m1v[c];
    g_scale1[c] = sc;
    g_shift1[c] = -mu * sc;
}

__global__ void fin2_kernel(const float* __restrict__ a2) {  // <<<1,64>>>
    int c = threadIdx.x;
    const float invN = 1.f / 65536.f;
    float bias = 0.f;
    for (int k = 0; k < 8; ++k) {
        float s = 0.f, q = 0.f;
        for (int b = 0; b < 64; ++b) { float2 v = g_part2[(k * 64 + c) * 64 + b]; s += v.x; q += v.y; }
        float mu  = s * invN;
        float var = q * invN - mu * mu;
        float wk  = a2[k] * rsqrtf(var + EPSV);
        g_scaleP[k * 64 + c] = wk;
        bias -= wk * mu;
    }
    g_biasP[c] = bias;
}

// ---------------------------------------------------------------------------
// Combine: out = sum_k scaleP[k,c]*P_k + biasP[c], float4-vectorized.
// MODE 0: -> g_N1
// MODE 1: -> g_N2, + avgpool3(g_N1)*cm (count_include_pad=False)
// MODE 2: -> out,  + xin*cm
// MODE 3: -> out += acc
// ---------------------------------------------------------------------------
template <int MODE>
__global__ __launch_bounds__(256)
void combine_kernel(const float* __restrict__ xin, float* __restrict__ out) {
    int bc = blockIdx.x;
    int b = bc >> 6, c = bc & 63;
    int t = threadIdx.x;
    float sp[8];
#pragma unroll
    for (int k = 0; k < 8; ++k) sp[k] = g_scaleP[k * 64 + c];
    float bias = g_biasP[c];
    float cmv  = g_cmv[c];
    size_t base = ((size_t)b * 64 + c) << 10;
    int p0 = t << 2;

    float4 acc = make_float4(bias, bias, bias, bias);
#pragma unroll
    for (int k = 0; k < 8; ++k) {
        float4 v = *reinterpret_cast<const float4*>(
            &g_P[(((size_t)k * 64 + b) * 64 + c) * 1024 + p0]);
        acc.x = fmaf(sp[k], v.x, acc.x);
        acc.y = fmaf(sp[k], v.y, acc.y);
        acc.z = fmaf(sp[k], v.z, acc.z);
        acc.w = fmaf(sp[k], v.w, acc.w);
    }

    if (MODE == 0) {
        *reinterpret_cast<float4*>(&g_N1[base + p0]) = acc;
    }
    if (MODE == 1) {
        int y = p0 >> 5, x = p0 & 31;
        int y0 = max(y - 1, 0), y1 = min(y + 1, 31);
        float rs[6];
#pragma unroll
        for (int j = 0; j < 6; ++j) {
            int xx = x - 1 + j;
            float v = 0.f;
            if ((unsigned)xx < 32u)
                for (int yy = y0; yy <= y1; ++yy) v += g_N1[base + (yy << 5) + xx];
            rs[j] = v;
        }
        float nr = (float)(y1 - y0 + 1);
        float pool[4];
#pragma unroll
        for (int i = 0; i < 4; ++i) {
            int xi = x + i;
            int c0 = max(xi - 1, 0), c1 = min(xi + 1, 31);
            float cnt = nr * (float)(c1 - c0 + 1);
            pool[i] = (rs[i] + rs[i + 1] + rs[i + 2]) / cnt;
        }
        acc.x += pool[0] * cmv; acc.y += pool[1] * cmv;
        acc.z += pool[2] * cmv; acc.w += pool[3] * cmv;
        *reinterpret_cast<float4*>(&g_N2[base + p0]) = acc;
    }
    if (MODE == 2) {
        float4 xv = *reinterpret_cast<const float4*>(&xin[base + p0]);
        acc.x += xv.x * cmv; acc.y += xv.y * cmv;
        acc.z += xv.z * cmv; acc.w += xv.w * cmv;
        *reinterpret_cast<float4*>(&out[base + p0]) = acc;
    }
    if (MODE == 3) {
        float4 ov = *reinterpret_cast<float4*>(&out[base + p0]);
        acc.x += ov.x; acc.y += ov.y; acc.z += ov.z; acc.w += ov.w;
        *reinterpret_cast<float4*>(&out[base + p0]) = acc;
    }
}

// ---------------------------------------------------------------------------
extern "C" void kernel_launch(void* const* d_in, const int* in_sizes, int n_in,
                              void* d_out, int out_size) {
    (void)in_sizes; (void)n_in; (void)out_size;
    const float* x    = (const float*)d_in[0];
    const float* a1   = (const float*)d_in[1];
    const float* a2   = (const float*)d_in[2];
    const float* W1_0 = (const float*)d_in[3];
    const float* W2_0 = (const float*)d_in[4];
    const float* W1_1 = (const float*)d_in[5];
    const float* W2_1 = (const float*)d_in[6];
    const float* W1_4 = (const float*)d_in[7];
    const float* W2_4 = (const float*)d_in[8];
    const float* W1_5 = (const float*)d_in[9];
    const float* W2_5 = (const float*)d_in[10];
    float* out = (float*)d_out;

    prep_kernel<<<1, 64>>>(a1, a2);

    // n1 = nor_conv(x, W1_0, W2_0)
    conv_kernel<1, 0><<<256, 256>>>(x, W1_0);
    fin1_kernel<<<1, 64>>>();
    conv_kernel<2, 0><<<256, 256>>>(nullptr, W2_0);
    fin2_kernel<<<1, 64>>>(a2);
    combine_kernel<0><<<4096, 256>>>(nullptr, nullptr);

    // n2 = nor_conv(x, W1_1, W2_1) + avgpool3(n1)*cm
    conv_kernel<1, 0><<<256, 256>>>(x, W1_1);
    fin1_kernel<<<1, 64>>>();
    conv_kernel<2, 0><<<256, 256>>>(nullptr, W2_1);
    fin2_kernel<<<1, 64>>>(a2);
    combine_kernel<1><<<4096, 256>>>(nullptr, nullptr);

    // out = x*cm + nor_conv(n1, W1_4, W2_4)
    conv_kernel<1, 1><<<256, 256>>>(nullptr, W1_4);
    fin1_kernel<<<1, 64>>>();
    conv_kernel<2, 0><<<256, 256>>>(nullptr, W2_4);
    fin2_kernel<<<1, 64>>>(a2);
    combine_kernel<2><<<4096, 256>>>(x, out);

    // out += nor_conv(n2, W1_5, W2_5)
    conv_kernel<1, 2><<<256, 256>>>(nullptr, W1_5);
    fin1_kernel<<<1, 64>>>();
    conv_kernel<2, 0><<<256, 256>>>(nullptr, W2_5);
    fin2_kernel<<<1, 64>>>(a2);
    combine_kernel<3><<<4096, 256>>>(nullptr, out);
}

// round 3
// speedup vs baseline: 1.1683x; 1.0027x over previous
#include <cuda_runtime.h>

// ---------------------------------------------------------------------------
// InferCellV1 on GB300 — fp32 with (a) prefix trick (8x FLOP cut), (b) packed
// fma.rn.f32x2 (2x FMA pipe), (c) BN stats fused into conv kernels,
// (d) float4 combine.
// ---------------------------------------------------------------------------

typedef unsigned long long u64;
#define EPSV 1e-5f

__device__ float  g_C1[(size_t)64 * 64 * 1024];          // conv1 out (16.7 MB)
__device__ float  g_P [(size_t)8 * 64 * 64 * 1024];      // prefix outs (134 MB)
__device__ float  g_N1[(size_t)64 * 64 * 1024];
__device__ float  g_N2[(size_t)64 * 64 * 1024];
__device__ float2 g_part1[64 * 64];                      // [c][b]
__device__ float2 g_part2[8 * 64 * 64];                  // [k][c][b]
__device__ float  g_scale1[64], g_shift1[64];
__device__ float  g_scaleP[8 * 64];
__device__ float  g_biasP[64];
__device__ float  g_m1v[64], g_cmv[64];

__device__ __forceinline__ u64 fma2(u64 a, u64 b, u64 c) {
    u64 d; asm("fma.rn.f32x2 %0, %1, %2, %3;" : "=l"(d) : "l"(a), "l"(b), "l"(c)); return d;
}
__device__ __forceinline__ u64 pack2(float x, float y) {
    u64 d; asm("mov.b64 %0, {%1, %2};" : "=l"(d) : "f"(x), "f"(y)); return d;
}
__device__ __forceinline__ float2 unpack2(u64 v) {
    float2 r; asm("mov.b64 {%0, %1}, %2;" : "=f"(r.x), "=f"(r.y) : "l"(v)); return r;
}

__global__ void prep_kernel(const float* __restrict__ a1, const float* __restrict__ a2) {
    int c = threadIdx.x;
    int g = c >> 3;
    float s1 = 0.f, s2 = 0.f;
    for (int i = g; i < 8; ++i) { s1 += a1[i]; s2 += a2[i]; }
    g_m1v[c] = s1;
    g_cmv[c] = s1 * s2;
}

// ---------------------------------------------------------------------------
// Direct 3x3 conv, one image b x 16 output channels x 32x32 per block.
// Thread: 4 pixels (rows ty+8p, col tx) x 16 oc, accumulated as 8 f32x2 pairs.
// STAGE 1: relu(src) -> conv -> g_C1, fused per-(c,b) stat partials.
// STAGE 2: affine(g_C1) -> conv, prefix P_k emitted per 8-ci group, fused
//          per-(k,c,b) stat partials.
// ---------------------------------------------------------------------------
template <int STAGE, int SRC>
__global__ __launch_bounds__(256, 2)
void conv_kernel(const float* __restrict__ in, const float* __restrict__ w) {
    __shared__ float sIn[9248];        // 8ci x 34x34 halo tile; reused as stat scratch
    __shared__ float sW[1152];         // [ci*9+tap][16 oc]  (oc pairs -> LDS.64)
    __shared__ float sSc[64], sSh[64];

    const int b   = blockIdx.x >> 2;
    const int oc0 = (blockIdx.x & 3) << 4;
    const int t   = threadIdx.x;
    const int tx  = t & 31;
    const int ty  = t >> 5;

    if (STAGE == 2 && t < 64) { sSc[t] = g_scale1[t]; sSh[t] = g_shift1[t]; }

    u64 acc2[4][8];
#pragma unroll
    for (int p = 0; p < 4; ++p)
#pragma unroll
        for (int o2 = 0; o2 < 8; ++o2) acc2[p][o2] = 0ull;

    const float* src = (STAGE == 2) ? g_C1
                     : (SRC == 0)   ? in
                     : (SRC == 1)   ? g_N1
                                    : g_N2;

    for (int cc = 0; cc < 8; ++cc) {
        const int cbase = cc << 3;
        __syncthreads();   // sIn is free to overwrite (covers prior group's readers)

        for (int idx = t; idx < 9248; idx += 256) {
            int ci = idx / 1156;
            int r  = idx - ci * 1156;
            int y  = r / 34;
            int x  = r - y * 34;
            int gy = y - 1, gx = x - 1;
            float v = 0.f;
            if ((unsigned)gy < 32u && (unsigned)gx < 32u) {
                float raw = src[(((size_t)b * 64 + cbase + ci) << 10) + (gy << 5) + gx];
                v = (STAGE == 1) ? fmaxf(raw, 0.f)
                                 : fmaf(raw, sSc[cbase + ci], sSh[cbase + ci]);
            }
            sIn[idx] = v;
        }
        for (int idx = t; idx < 1152; idx += 256) {
            int oc = idx & 15;
            int r  = idx >> 4;          // ci*9 + tap
            int ci = r / 9;
            int tap = r - ci * 9;
            sW[idx] = w[((size_t)(oc0 + oc) * 64 + cbase + ci) * 9 + tap];
        }
        __syncthreads();

#pragma unroll
        for (int ci = 0; ci < 8; ++ci) {
#pragma unroll
            for (int ky = 0; ky < 3; ++ky) {
#pragma unroll
                for (int kx = 0; kx < 3; ++kx) {
                    const float* wrow = &sW[(ci * 9 + ky * 3 + kx) << 4];
                    u64 wp[8];
#pragma unroll
                    for (int o2 = 0; o2 < 8; ++o2)
                        wp[o2] = *reinterpret_cast<const u64*>(wrow + (o2 << 1));
#pragma unroll
                    for (int p = 0; p < 4; ++p) {
                        float iv = sIn[ci * 1156 + (ty + (p << 3) + ky) * 34 + tx + kx];
                        u64 iv2 = pack2(iv, iv);
#pragma unroll
                        for (int o2 = 0; o2 < 8; ++o2)
                            acc2[p][o2] = fma2(iv2, wp[o2], acc2[p][o2]);
                    }
                }
            }
        }

        if (STAGE == 2) {
            // acc2 now holds prefix P_cc. Emit it + fused stat partials.
            float s[16], q[16];
#pragma unroll
            for (int o = 0; o < 16; ++o) { s[o] = 0.f; q[o] = 0.f; }
#pragma unroll
            for (int p = 0; p < 4; ++p) {
                int pix = ((ty + (p << 3)) << 5) + tx;
#pragma unroll
                for (int o2 = 0; o2 < 8; ++o2) {
                    float2 v = unpack2(acc2[p][o2]);
                    size_t base = (((size_t)cc * 64 + b) * 64 + oc0 + (o2 << 1)) * 1024 + pix;
                    g_P[base]        = v.x;
                    g_P[base + 1024] = v.y;
                    s[2 * o2]     += v.x; q[2 * o2]     += v.x * v.x;
                    s[2 * o2 + 1] += v.y; q[2 * o2 + 1] += v.y * v.y;
                }
            }
            __syncthreads();           // done reading sIn for conv
#pragma unroll
            for (int o = 0; o < 16; ++o) { sIn[o * 256 + t] = s[o]; sIn[4096 + o * 256 + t] = q[o]; }
            __syncthreads();
            for (int off = 128; off; off >>= 1) {
                if (t < off) {
#pragma unroll
                    for (int o = 0; o < 16; ++o) {
                        sIn[o * 256 + t]        += sIn[o * 256 + t + off];
                        sIn[4096 + o * 256 + t] += sIn[4096 + o * 256 + t + off];
                    }
                }
                __syncthreads();
            }
            if (t < 16)
                g_part2[(cc * 64 + oc0 + t) * 64 + b] =
                    make_float2(sIn[t * 256], sIn[4096 + t * 256]);
        }
    }

    if (STAGE == 1) {
        float s[16], q[16];
#pragma unroll
        for (int o = 0; o < 16; ++o) { s[o] = 0.f; q[o] = 0.f; }
#pragma unroll
        for (int p = 0; p < 4; ++p) {
            int pix = ((ty + (p << 3)) << 5) + tx;
#pragma unroll
            for (int o2 = 0; o2 < 8; ++o2) {
                float2 v = unpack2(acc2[p][o2]);
                size_t base = (((size_t)b * 64 + oc0 + (o2 << 1)) << 10) + pix;
                g_C1[base]        = v.x;
                g_C1[base + 1024] = v.y;
                s[2 * o2]     += v.x; q[2 * o2]     += v.x * v.x;
                s[2 * o2 + 1] += v.y; q[2 * o2 + 1] += v.y * v.y;
            }
        }
        __syncthreads();
#pragma unroll
        for (int o = 0; o < 16; ++o) { sIn[o * 256 + t] = s[o]; sIn[4096 + o * 256 + t] = q[o]; }
        __syncthreads();
        for (int off = 128; off; off >>= 1) {
            if (t < off) {
#pragma unroll
                for (int o = 0; o < 16; ++o) {
                    sIn[o * 256 + t]        += sIn[o * 256 + t + off];
                    sIn[4096 + o * 256 + t] += sIn[4096 + o * 256 + t + off];
                }
            }
            __syncthreads();
        }
        if (t < 16)
            g_part1[(oc0 + t) * 64 + b] = make_float2(sIn[t * 256], sIn[4096 + t * 256]);
    }
}

// ---------------------------------------------------------------------------
__global__ void fin1_kernel() {  // <<<1,64>>>
    int c = threadIdx.x;
    float s = 0.f, q = 0.f;
    for (int b = 0; b < 64; ++b) { float2 v = g_part1[c * 64 + b]; s += v.x; q += v.y; }
    const float invN = 1.f / 65536.f;
    float mu   = s * invN;
    float var  = q * invN - mu * mu;
    float sc   = rsqrtf(var + EPSV) * g_m1v[c];
    g_scale1[c] = sc;
    g_shift1[c] = -mu * sc;
}

__global__ void fin2_kernel(const float* __restrict__ a2) {  // <<<1,64>>>
    int c = threadIdx.x;
    const float invN = 1.f / 65536.f;
    float bias = 0.f;
    for (int k = 0; k < 8; ++k) {
        float s = 0.f, q = 0.f;
        for (int b = 0; b < 64; ++b) { float2 v = g_part2[(k * 64 + c) * 64 + b]; s += v.x; q += v.y; }
        float mu  = s * invN;
        float var = q * invN - mu * mu;
        float wk  = a2[k] * rsqrtf(var + EPSV);
        g_scaleP[k * 64 + c] = wk;
        bias -= wk * mu;
    }
    g_biasP[c] = bias;
}

// ---------------------------------------------------------------------------
// Combine: out = sum_k scaleP[k,c]*P_k + biasP[c], float4-vectorized.
// MODE 0: -> g_N1
// MODE 1: -> g_N2, + avgpool3(g_N1)*cm (count_include_pad=False)
// MODE 2: -> out,  + xin*cm
// MODE 3: -> out += acc
// ---------------------------------------------------------------------------
template <int MODE>
__global__ __launch_bounds__(256)
void combine_kernel(const float* __restrict__ xin, float* __restrict__ out) {
    int bc = blockIdx.x;
    int b = bc >> 6, c = bc & 63;
    int t = threadIdx.x;
    float sp[8];
#pragma unroll
    for (int k = 0; k < 8; ++k) sp[k] = g_scaleP[k * 64 + c];
    float bias = g_biasP[c];
    float cmv  = g_cmv[c];
    size_t base = ((size_t)b * 64 + c) << 10;
    int p0 = t << 2;

    float4 acc = make_float4(bias, bias, bias, bias);
#pragma unroll
    for (int k = 0; k < 8; ++k) {
        float4 v = *reinterpret_cast<const float4*>(
            &g_P[(((size_t)k * 64 + b) * 64 + c) * 1024 + p0]);
        acc.x = fmaf(sp[k], v.x, acc.x);
        acc.y = fmaf(sp[k], v.y, acc.y);
        acc.z = fmaf(sp[k], v.z, acc.z);
        acc.w = fmaf(sp[k], v.w, acc.w);
    }

    if (MODE == 0) {
        *reinterpret_cast<float4*>(&g_N1[base + p0]) = acc;
    }
    if (MODE == 1) {
        int y = p0 >> 5, x = p0 & 31;
        int y0 = max(y - 1, 0), y1 = min(y + 1, 31);
        float rs[6];
#pragma unroll
        for (int j = 0; j < 6; ++j) {
            int xx = x - 1 + j;
            float v = 0.f;
            if ((unsigned)xx < 32u)
                for (int yy = y0; yy <= y1; ++yy) v += g_N1[base + (yy << 5) + xx];
            rs[j] = v;
        }
        float nr = (float)(y1 - y0 + 1);
        float pool[4];
#pragma unroll
        for (int i = 0; i < 4; ++i) {
            int xi = x + i;
            int c0 = max(xi - 1, 0), c1 = min(xi + 1, 31);
            float cnt = nr * (float)(c1 - c0 + 1);
            pool[i] = (rs[i] + rs[i + 1] + rs[i + 2]) / cnt;
        }
        acc.x += pool[0] * cmv; acc.y += pool[1] * cmv;
        acc.z += pool[2] * cmv; acc.w += pool[3] * cmv;
        *reinterpret_cast<float4*>(&g_N2[base + p0]) = acc;
    }
    if (MODE == 2) {
        float4 xv = *reinterpret_cast<const float4*>(&xin[base + p0]);
        acc.x += xv.x * cmv; acc.y += xv.y * cmv;
        acc.z += xv.z * cmv; acc.w += xv.w * cmv;
        *reinterpret_cast<float4*>(&out[base + p0]) = acc;
    }
    if (MODE == 3) {
        float4 ov = *reinterpret_cast<float4*>(&out[base + p0]);
        acc.x += ov.x; acc.y += ov.y; acc.z += ov.z; acc.w += ov.w;
        *reinterpret_cast<float4*>(&out[base + p0]) = acc;
    }
}

// ---------------------------------------------------------------------------
extern "C" void kernel_launch(void* const* d_in, const int* in_sizes, int n_in,
                              void* d_out, int out_size) {
    (void)in_sizes; (void)n_in; (void)out_size;
    const float* x    = (const float*)d_in[0];
    const float* a1   = (const float*)d_in[1];
    const float* a2   = (const float*)d_in[2];
    const float* W1_0 = (const float*)d_in[3];
    const float* W2_0 = (const float*)d_in[4];
    const float* W1_1 = (const float*)d_in[5];
    const float* W2_1 = (const float*)d_in[6];
    const float* W1_4 = (const float*)d_in[7];
    const float* W2_4 = (const float*)d_in[8];
    const float* W1_5 = (const float*)d_in[9];
    const float* W2_5 = (const float*)d_in[10];
    float* out = (float*)d_out;

    prep_kernel<<<1, 64>>>(a1, a2);

    // n1 = nor_conv(x, W1_0, W2_0)
    conv_kernel<1, 0><<<256, 256>>>(x, W1_0);
    fin1_kernel<<<1, 64>>>();
    conv_kernel<2, 0><<<256, 256>>>(nullptr, W2_0);
    fin2_kernel<<<1, 64>>>(a2);
    combine_kernel<0><<<4096, 256>>>(nullptr, nullptr);

    // n2 = nor_conv(x, W1_1, W2_1) + avgpool3(n1)*cm
    conv_kernel<1, 0><<<256, 256>>>(x, W1_1);
    fin1_kernel<<<1, 64>>>();
    conv_kernel<2, 0><<<256, 256>>>(nullptr, W2_1);
    fin2_kernel<<<1, 64>>>(a2);
    combine_kernel<1><<<4096, 256>>>(nullptr, nullptr);

    // out = x*cm + nor_conv(n1, W1_4, W2_4)
    conv_kernel<1, 1><<<256, 256>>>(nullptr, W1_4);
    fin1_kernel<<<1, 64>>>();
    conv_kernel<2, 0><<<256, 256>>>(nullptr, W2_4);
    fin2_kernel<<<1, 64>>>(a2);
    combine_kernel<2><<<4096, 256>>>(x, out);

    // out += nor_conv(n2, W1_5, W2_5)
    conv_kernel<1, 2><<<256, 256>>>(nullptr, W1_5);
    fin1_kernel<<<1, 64>>>();
    conv_kernel<2, 0><<<256, 256>>>(nullptr, W2_5);
    fin2_kernel<<<1, 64>>>(a2);
    combine_kernel<3><<<4096, 256>>>(nullptr, out);
}